// round 7
// baseline (speedup 1.0000x reference)
#include <cuda_runtime.h>
#include <cuda_bf16.h>
#include <cstdint>

#define NN 50000
#define EE 800000
#define DIM 128   // IN == H*C == 128
#define NB 49     // ceil(NN/1024)

// ---------------- scratch -----------------------------------------------------
__device__ float          g_q[(size_t)NN * DIM];
__device__ __nv_bfloat16  g_kb[(size_t)NN * DIM];
__device__ __nv_bfloat16  g_vb[(size_t)NN * DIM];
__device__ int   g_deg[NN];
__device__ int   g_cursor[NN];
__device__ int   g_off[NN + 1];
__device__ int   g_csr[EE];
__device__ int   g_bsum[NB];
__device__ int   g_bpre[NB];
__device__ int   g_is32;   // 1 if edge_index buffer is int32, 0 if int64

// ---------------- init + dtype detection -------------------------------------
__global__ void init_kernel() {
    int i = blockIdx.x * blockDim.x + threadIdx.x;
    if (i < NN) { g_deg[i] = 0; g_cursor[i] = 0; }
    if (i == 0) g_is32 = 0;
}

// Reference declares int64 but JAX default (x64 off) silently yields int32.
__global__ void detect_kernel(const void* __restrict__ ei) {
    long long v = ((const long long*)ei)[threadIdx.x];   // 1024 threads
    if (v < 0 || v >= (long long)NN) g_is32 = 1;
}

__device__ __forceinline__ int edge_src(const void* ei, int e) {
    if (g_is32) return ((const int*)ei)[e];
    return (int)((const long long*)ei)[e];
}
__device__ __forceinline__ int edge_dst(const void* ei, int e) {
    if (g_is32) return ((const int*)ei)[EE + e];
    return (int)((const long long*)ei)[EE + e];
}

// ---------------- CSR build ---------------------------------------------------
__global__ void hist_kernel(const void* __restrict__ ei) {
    int e = blockIdx.x * blockDim.x + threadIdx.x;
    if (e < EE) {
        int dst = edge_dst(ei, e);
        if ((unsigned)dst < (unsigned)NN)
            atomicAdd(&g_deg[dst], 1);
    }
}

// 3-phase parallel exclusive scan of g_deg -> g_off
__global__ void scan1_kernel() {
    __shared__ int wsum[32];
    int tid = threadIdx.x, lane = tid & 31, wid = tid >> 5;
    int i = blockIdx.x * 1024 + tid;
    int v = (i < NN) ? g_deg[i] : 0;
    int s = v;
    #pragma unroll
    for (int d = 1; d < 32; d <<= 1) {
        int t = __shfl_up_sync(0xffffffffu, s, d);
        if (lane >= d) s += t;
    }
    if (lane == 31) wsum[wid] = s;
    __syncthreads();
    if (wid == 0) {
        int ws = wsum[lane];
        #pragma unroll
        for (int d = 1; d < 32; d <<= 1) {
            int t = __shfl_up_sync(0xffffffffu, ws, d);
            if (lane >= d) ws += t;
        }
        wsum[lane] = ws;
    }
    __syncthreads();
    int excl = (s - v) + (wid ? wsum[wid - 1] : 0);
    if (i < NN) g_off[i] = excl;
    if (tid == 1023) g_bsum[blockIdx.x] = excl + v;
}

__global__ void scan2_kernel() {   // 1 block, 64 threads (NB=49)
    __shared__ int w0;
    int t = threadIdx.x, lane = t & 31;
    int v = (t < NB) ? g_bsum[t] : 0;
    int s = v;
    #pragma unroll
    for (int d = 1; d < 32; d <<= 1) {
        int x = __shfl_up_sync(0xffffffffu, s, d);
        if (lane >= d) s += x;
    }
    if (t == 31) w0 = s;
    __syncthreads();
    int incl = s + ((t >= 32) ? w0 : 0);
    if (t < NB) g_bpre[t] = incl - v;
    if (t == 63) g_off[NN] = incl;
}

__global__ void scan3_kernel() {
    int i = blockIdx.x * 1024 + threadIdx.x;
    if (i < NN) g_off[i] += g_bpre[i >> 10];
}

__global__ void fill_kernel(const void* __restrict__ ei) {
    int e = blockIdx.x * blockDim.x + threadIdx.x;
    if (e < EE) {
        int src = edge_src(ei, e);
        int dst = edge_dst(ei, e);
        if ((unsigned)dst < (unsigned)NN && (unsigned)src < (unsigned)NN) {
            int pos = g_off[dst] + atomicAdd(&g_cursor[dst], 1);
            if ((unsigned)pos < (unsigned)EE)
                g_csr[pos] = src;
        }
    }
}

// ---------------- bf16x3 tensor-core GEMM ------------------------------------
// fp32 a = a_hi(bf16) + a_lo(bf16); D += Ahi*Bhi + Ahi*Blo + Alo*Bhi.
// Splits done once at tile load; mainloop = LDS + MMA only.
__device__ __forceinline__ void mma16(float* c, const uint32_t* a, uint32_t b0, uint32_t b1) {
    asm("mma.sync.aligned.m16n8k16.row.col.f32.bf16.bf16.f32 "
        "{%0,%1,%2,%3},{%4,%5,%6,%7},{%8,%9},{%0,%1,%2,%3};"
        : "+f"(c[0]), "+f"(c[1]), "+f"(c[2]), "+f"(c[3])
        : "r"(a[0]), "r"(a[1]), "r"(a[2]), "r"(a[3]), "r"(b0), "r"(b1));
}

#define KC 32
#define SSTR 40   // smem row stride in bf16; banks (20g+tg)%32 all-distinct

// y = x @ W + b.  grid.y: 0->g_q(f32) 1->g_kb(bf16) 2->g_vb(bf16) 3->dout(f32)
__global__ __launch_bounds__(256) void gemm_bf16x3_kernel(
    const float* __restrict__ x,
    const float* __restrict__ Wq, const float* __restrict__ bq,
    const float* __restrict__ Wk, const float* __restrict__ bk,
    const float* __restrict__ Wv, const float* __restrict__ bv,
    const float* __restrict__ Ws, const float* __restrict__ bs,
    float* __restrict__ dout)
{
    const float* W; const float* bias;
    float* outf = nullptr; __nv_bfloat16* outb = nullptr;
    switch (blockIdx.y) {
        case 0:  W = Wq; bias = bq; outf = g_q;  break;
        case 1:  W = Wk; bias = bk; outb = g_kb; break;
        case 2:  W = Wv; bias = bv; outb = g_vb; break;
        default: W = Ws; bias = bs; outf = dout; break;
    }

    __shared__ __nv_bfloat16 xs_hi[128][SSTR];  // A tile [m][k]
    __shared__ __nv_bfloat16 xs_lo[128][SSTR];
    __shared__ __nv_bfloat16 wt_hi[128][SSTR];  // B tile transposed [n][k]
    __shared__ __nv_bfloat16 wt_lo[128][SSTR];

    const int tid = threadIdx.x;
    const int lane = tid & 31, wid = tid >> 5;
    const int warp_m = wid >> 1;    // 0..3 -> 32 rows each
    const int warp_n = wid & 1;     // 0..1 -> 64 cols each
    const int m_base = blockIdx.x * 128;
    const int g  = lane >> 2;       // group 0..7
    const int tg = lane & 3;        // thread-in-group

    float acc[2][8][4];
    #pragma unroll
    for (int a = 0; a < 2; a++)
        #pragma unroll
        for (int b = 0; b < 8; b++)
            #pragma unroll
            for (int c = 0; c < 4; c++) acc[a][b][c] = 0.f;

    for (int kc = 0; kc < DIM; kc += KC) {
        // ---- A tile: 128 rows x KC cols, split to hi/lo bf16 ----
        #pragma unroll
        for (int i = 0; i < 4; i++) {
            int id  = tid + i * 256;       // 1024 float4 slots
            int row = id >> 3;
            int c4  = (id & 7) * 4;
            float4 v = make_float4(0.f, 0.f, 0.f, 0.f);
            int grow = m_base + row;
            if (grow < NN) v = *(const float4*)(x + (size_t)grow * DIM + kc + c4);
            __nv_bfloat162 h01 = __floats2bfloat162_rn(v.x, v.y);
            __nv_bfloat162 h23 = __floats2bfloat162_rn(v.z, v.w);
            float2 f01 = __bfloat1622float2(h01);
            float2 f23 = __bfloat1622float2(h23);
            __nv_bfloat162 l01 = __floats2bfloat162_rn(v.x - f01.x, v.y - f01.y);
            __nv_bfloat162 l23 = __floats2bfloat162_rn(v.z - f23.x, v.w - f23.y);
            *(__nv_bfloat162*)&xs_hi[row][c4]     = h01;
            *(__nv_bfloat162*)&xs_hi[row][c4 + 2] = h23;
            *(__nv_bfloat162*)&xs_lo[row][c4]     = l01;
            *(__nv_bfloat162*)&xs_lo[row][c4 + 2] = l23;
        }
        // ---- B tile: KC rows x 128 cols, split + transpose to [n][k] ----
        #pragma unroll
        for (int i = 0; i < 4; i++) {
            int id   = tid + i * 256;
            int krow = id >> 5;            // 0..31
            int n4   = (id & 31) * 4;      // 0..124
            float4 v = *(const float4*)(W + (size_t)(kc + krow) * DIM + n4);
            float vv[4] = {v.x, v.y, v.z, v.w};
            #pragma unroll
            for (int j = 0; j < 4; j++) {
                __nv_bfloat16 h = __float2bfloat16_rn(vv[j]);
                __nv_bfloat16 l = __float2bfloat16_rn(vv[j] - __bfloat162float(h));
                wt_hi[n4 + j][krow] = h;
                wt_lo[n4 + j][krow] = l;
            }
        }
        __syncthreads();

        #pragma unroll
        for (int kk = 0; kk < KC; kk += 16) {
            uint32_t ahi[2][4], alo[2][4];
            #pragma unroll
            for (int tm = 0; tm < 2; tm++) {
                int r0 = warp_m * 32 + tm * 16 + g;
                int k0 = kk + 2 * tg;
                ahi[tm][0] = *(const uint32_t*)&xs_hi[r0    ][k0    ];
                ahi[tm][1] = *(const uint32_t*)&xs_hi[r0 + 8][k0    ];
                ahi[tm][2] = *(const uint32_t*)&xs_hi[r0    ][k0 + 8];
                ahi[tm][3] = *(const uint32_t*)&xs_hi[r0 + 8][k0 + 8];
                alo[tm][0] = *(const uint32_t*)&xs_lo[r0    ][k0    ];
                alo[tm][1] = *(const uint32_t*)&xs_lo[r0 + 8][k0    ];
                alo[tm][2] = *(const uint32_t*)&xs_lo[r0    ][k0 + 8];
                alo[tm][3] = *(const uint32_t*)&xs_lo[r0 + 8][k0 + 8];
            }
            #pragma unroll
            for (int tn = 0; tn < 8; tn++) {
                int n0 = warp_n * 64 + tn * 8 + g;
                int k0 = kk + 2 * tg;
                uint32_t bhi0 = *(const uint32_t*)&wt_hi[n0][k0    ];
                uint32_t bhi1 = *(const uint32_t*)&wt_hi[n0][k0 + 8];
                uint32_t blo0 = *(const uint32_t*)&wt_lo[n0][k0    ];
                uint32_t blo1 = *(const uint32_t*)&wt_lo[n0][k0 + 8];
                #pragma unroll
                for (int tm = 0; tm < 2; tm++) {
                    mma16(acc[tm][tn], ahi[tm], bhi0, bhi1);   // hi*hi
                    mma16(acc[tm][tn], ahi[tm], blo0, blo1);   // hi*lo
                    mma16(acc[tm][tn], alo[tm], bhi0, bhi1);   // lo*hi
                }
            }
        }
        __syncthreads();
    }

    // epilogue: bias + store (fp32 or bf16 depending on output)
    #pragma unroll
    for (int tm = 0; tm < 2; tm++) {
        int r = m_base + warp_m * 32 + tm * 16 + g;
        #pragma unroll
        for (int tn = 0; tn < 8; tn++) {
            int c = warp_n * 64 + tn * 8 + tg * 2;
            float b0 = bias[c], b1 = bias[c + 1];
            float v00 = acc[tm][tn][0] + b0, v01 = acc[tm][tn][1] + b1;
            float v10 = acc[tm][tn][2] + b0, v11 = acc[tm][tn][3] + b1;
            if (outf) {
                if (r < NN)
                    *(float2*)(outf + (size_t)r * DIM + c) = make_float2(v00, v01);
                if (r + 8 < NN)
                    *(float2*)(outf + (size_t)(r + 8) * DIM + c) = make_float2(v10, v11);
            } else {
                if (r < NN)
                    *(__nv_bfloat162*)(outb + (size_t)r * DIM + c) =
                        __floats2bfloat162_rn(v00, v01);
                if (r + 8 < NN)
                    *(__nv_bfloat162*)(outb + (size_t)(r + 8) * DIM + c) =
                        __floats2bfloat162_rn(v10, v11);
            }
        }
    }
}

// ---------------- fused attention: one warp per dst node ---------------------
__global__ void attn_kernel(float* __restrict__ dout) {
    int warp = (blockIdx.x * blockDim.x + threadIdx.x) >> 5;
    if (warp >= NN) return;
    int lane = threadIdx.x & 31;

    const float4 qv = *(const float4*)(g_q + (size_t)warp * DIM + lane * 4);
    float4 acc = make_float4(0.f, 0.f, 0.f, 0.f);
    float denom = 0.f;

    const int e0 = g_off[warp];
    const int e1 = g_off[warp + 1];
    const float inv_sqrt_c = 0.17677669529663688f;  // 1/sqrt(32)

    for (int j = e0; j < e1; ++j) {
        int s = g_csr[j];
        uint2 kr = *(const uint2*)(g_kb + (size_t)s * DIM + lane * 4);
        float2 k01 = __bfloat1622float2(*(__nv_bfloat162*)&kr.x);
        float2 k23 = __bfloat1622float2(*(__nv_bfloat162*)&kr.y);
        float p = qv.x * k01.x + qv.y * k01.y + qv.z * k23.x + qv.w * k23.y;
        p += __shfl_xor_sync(0xffffffffu, p, 1);
        p += __shfl_xor_sync(0xffffffffu, p, 2);
        p += __shfl_xor_sync(0xffffffffu, p, 4);
        float ex = __expf(p * inv_sqrt_c);
        uint2 vr = *(const uint2*)(g_vb + (size_t)s * DIM + lane * 4);
        float2 v01 = __bfloat1622float2(*(__nv_bfloat162*)&vr.x);
        float2 v23 = __bfloat1622float2(*(__nv_bfloat162*)&vr.y);
        acc.x += ex * v01.x; acc.y += ex * v01.y;
        acc.z += ex * v23.x; acc.w += ex * v23.y;
        denom += ex;
    }

    float inv = (denom > 0.f) ? (1.f / denom) : 0.f;
    float4* op = (float4*)(dout + (size_t)warp * DIM + lane * 4);
    float4 cur = *op;   // skip projection from GEMM
    cur.x += acc.x * inv; cur.y += acc.y * inv;
    cur.z += acc.z * inv; cur.w += acc.w * inv;
    *op = cur;
}

// ---------------- launch: fork-join so CSR build overlaps the GEMM ------------
extern "C" void kernel_launch(void* const* d_in, const int* in_sizes, int n_in,
                              void* d_out, int out_size) {
    const float* x   = (const float*)d_in[0];
    const void*  ei  = d_in[1];
    const float* Wq  = (const float*)d_in[2];
    const float* bq  = (const float*)d_in[3];
    const float* Wk  = (const float*)d_in[4];
    const float* bk  = (const float*)d_in[5];
    const float* Wv  = (const float*)d_in[6];
    const float* bv  = (const float*)d_in[7];
    const float* Ws  = (const float*)d_in[8];
    const float* bs  = (const float*)d_in[9];
    float* dout = (float*)d_out;

    cudaStream_t s2;
    cudaStreamCreateWithFlags(&s2, cudaStreamNonBlocking);
    cudaEvent_t ev_fork, ev_join;
    cudaEventCreateWithFlags(&ev_fork, cudaEventDisableTiming);
    cudaEventCreateWithFlags(&ev_join, cudaEventDisableTiming);

    cudaEventRecord(ev_fork, 0);
    cudaStreamWaitEvent(s2, ev_fork, 0);

    // side stream: CSR build chain
    init_kernel<<<(NN + 1023) / 1024, 1024, 0, s2>>>();
    detect_kernel<<<1, 1024, 0, s2>>>(ei);
    hist_kernel<<<(EE + 255) / 256, 256, 0, s2>>>(ei);
    scan1_kernel<<<NB, 1024, 0, s2>>>();
    scan2_kernel<<<1, 64, 0, s2>>>();
    scan3_kernel<<<NB, 1024, 0, s2>>>();
    fill_kernel<<<(EE + 255) / 256, 256, 0, s2>>>(ei);
    cudaEventRecord(ev_join, s2);

    // main stream: GEMM runs concurrently with CSR build
    dim3 ggrid((NN + 127) / 128, 4);
    gemm_bf16x3_kernel<<<ggrid, 256>>>(x, Wq, bq, Wk, bk, Wv, bv, Ws, bs, dout);

    cudaStreamWaitEvent(0, ev_join, 0);
    attn_kernel<<<(NN * 32 + 255) / 256, 256>>>(dout);
}

// round 12
// speedup vs baseline: 1.3949x; 1.3949x over previous
#include <cuda_runtime.h>
#include <cuda_bf16.h>
#include <cstdint>

#define NN 50000
#define EE 800000
#define DIM 128   // IN == H*C == 128
#define NB 49     // ceil(NN/1024)

// ---------------- scratch -----------------------------------------------------
__device__ float          g_q[(size_t)NN * DIM];
__device__ __nv_bfloat16  g_kb[(size_t)NN * DIM];
__device__ __nv_bfloat16  g_vb[(size_t)NN * DIM];
__device__ int   g_deg[NN];
__device__ int   g_cursor[NN];
__device__ int   g_off[NN + 1];
__device__ int   g_csr[EE];
__device__ int   g_bsum[NB];
__device__ int   g_bpre[NB];
__device__ int   g_is32;

// ---------------- init + dtype detection -------------------------------------
__global__ void init_kernel() {
    int i = blockIdx.x * blockDim.x + threadIdx.x;
    if (i < NN) { g_deg[i] = 0; g_cursor[i] = 0; }
    if (i == 0) g_is32 = 0;
}

// Reference declares int64 but JAX default (x64 off) silently yields int32.
__global__ void detect_kernel(const void* __restrict__ ei) {
    long long v = ((const long long*)ei)[threadIdx.x];   // 1024 threads
    if (v < 0 || v >= (long long)NN) g_is32 = 1;
}

__device__ __forceinline__ int edge_src(const void* ei, int e) {
    if (g_is32) return ((const int*)ei)[e];
    return (int)((const long long*)ei)[e];
}
__device__ __forceinline__ int edge_dst(const void* ei, int e) {
    if (g_is32) return ((const int*)ei)[EE + e];
    return (int)((const long long*)ei)[EE + e];
}

// ---------------- CSR build ---------------------------------------------------
__global__ void hist_kernel(const void* __restrict__ ei) {
    int e = blockIdx.x * blockDim.x + threadIdx.x;
    if (e < EE) {
        int dst = edge_dst(ei, e);
        if ((unsigned)dst < (unsigned)NN)
            atomicAdd(&g_deg[dst], 1);
    }
}

__global__ void scan1_kernel() {
    __shared__ int wsum[32];
    int tid = threadIdx.x, lane = tid & 31, wid = tid >> 5;
    int i = blockIdx.x * 1024 + tid;
    int v = (i < NN) ? g_deg[i] : 0;
    int s = v;
    #pragma unroll
    for (int d = 1; d < 32; d <<= 1) {
        int t = __shfl_up_sync(0xffffffffu, s, d);
        if (lane >= d) s += t;
    }
    if (lane == 31) wsum[wid] = s;
    __syncthreads();
    if (wid == 0) {
        int ws = wsum[lane];
        #pragma unroll
        for (int d = 1; d < 32; d <<= 1) {
            int t = __shfl_up_sync(0xffffffffu, ws, d);
            if (lane >= d) ws += t;
        }
        wsum[lane] = ws;
    }
    __syncthreads();
    int excl = (s - v) + (wid ? wsum[wid - 1] : 0);
    if (i < NN) g_off[i] = excl;
    if (tid == 1023) g_bsum[blockIdx.x] = excl + v;
}

__global__ void scan2_kernel() {   // 1 block, 64 threads (NB=49)
    __shared__ int w0;
    int t = threadIdx.x, lane = t & 31;
    int v = (t < NB) ? g_bsum[t] : 0;
    int s = v;
    #pragma unroll
    for (int d = 1; d < 32; d <<= 1) {
        int x = __shfl_up_sync(0xffffffffu, s, d);
        if (lane >= d) s += x;
    }
    if (t == 31) w0 = s;
    __syncthreads();
    int incl = s + ((t >= 32) ? w0 : 0);
    if (t < NB) g_bpre[t] = incl - v;
    if (t == 63) g_off[NN] = incl;
}

__global__ void scan3_kernel() {
    int i = blockIdx.x * 1024 + threadIdx.x;
    if (i < NN) g_off[i] += g_bpre[i >> 10];
}

__global__ void fill_kernel(const void* __restrict__ ei) {
    int e = blockIdx.x * blockDim.x + threadIdx.x;
    if (e < EE) {
        int src = edge_src(ei, e);
        int dst = edge_dst(ei, e);
        if ((unsigned)dst < (unsigned)NN && (unsigned)src < (unsigned)NN) {
            int pos = g_off[dst] + atomicAdd(&g_cursor[dst], 1);
            if ((unsigned)pos < (unsigned)EE)
                g_csr[pos] = src;
        }
    }
}

// ---------------- bf16x3 GEMM with ldmatrix (conflict-free) -------------------
// fp32 = hi(bf16) + lo(bf16); D += Ahi*Bhi + Ahi*Blo + Alo*Bhi (lo*lo ~2^-17).
// A stored [m][k] (stride 40 bf16 = 80B: 20-bank rows, perfect partition).
// B stored [k][n] untransposed (stride 136 bf16 = 272B: 68-bank rows, perfect
// partition); transpose happens in ldmatrix.x2.trans at fragment load.
__device__ __forceinline__ uint32_t smem_u32(const void* p) {
    uint32_t a;
    asm("{ .reg .u64 t; cvta.to.shared.u64 t, %1; cvt.u32.u64 %0, t; }"
        : "=r"(a) : "l"(p));
    return a;
}
__device__ __forceinline__ void ldmA(uint32_t* r, uint32_t addr) {
    asm volatile("ldmatrix.sync.aligned.m8n8.x4.shared.b16 {%0,%1,%2,%3}, [%4];"
                 : "=r"(r[0]), "=r"(r[1]), "=r"(r[2]), "=r"(r[3]) : "r"(addr));
}
__device__ __forceinline__ void ldmB(uint32_t& b0, uint32_t& b1, uint32_t addr) {
    asm volatile("ldmatrix.sync.aligned.m8n8.x2.trans.shared.b16 {%0,%1}, [%2];"
                 : "=r"(b0), "=r"(b1) : "r"(addr));
}
__device__ __forceinline__ void mma16(float* c, const uint32_t* a, uint32_t b0, uint32_t b1) {
    asm("mma.sync.aligned.m16n8k16.row.col.f32.bf16.bf16.f32 "
        "{%0,%1,%2,%3},{%4,%5,%6,%7},{%8,%9},{%0,%1,%2,%3};"
        : "+f"(c[0]), "+f"(c[1]), "+f"(c[2]), "+f"(c[3])
        : "r"(a[0]), "r"(a[1]), "r"(a[2]), "r"(a[3]), "r"(b0), "r"(b1));
}

#define KC   32
#define ASTR 40    // A row stride in bf16 (80B)
#define BSTR 136   // B row stride in bf16 (272B)

// y = x @ W + b.  grid.y: 0->g_q(f32) 1->g_kb(bf16) 2->g_vb(bf16) 3->dout(f32)
__global__ __launch_bounds__(256) void gemm_bf16x3_kernel(
    const float* __restrict__ x,
    const float* __restrict__ Wq, const float* __restrict__ bq,
    const float* __restrict__ Wk, const float* __restrict__ bk,
    const float* __restrict__ Wv, const float* __restrict__ bv,
    const float* __restrict__ Ws, const float* __restrict__ bs,
    float* __restrict__ dout)
{
    const float* W; const float* bias;
    float* outf = nullptr; __nv_bfloat16* outb = nullptr;
    switch (blockIdx.y) {
        case 0:  W = Wq; bias = bq; outf = g_q;  break;
        case 1:  W = Wk; bias = bk; outb = g_kb; break;
        case 2:  W = Wv; bias = bv; outb = g_vb; break;
        default: W = Ws; bias = bs; outf = dout; break;
    }

    __shared__ __nv_bfloat16 a_hi[128 * ASTR];
    __shared__ __nv_bfloat16 a_lo[128 * ASTR];
    __shared__ __nv_bfloat16 b_hi[KC * BSTR];
    __shared__ __nv_bfloat16 b_lo[KC * BSTR];

    const int tid = threadIdx.x;
    const int lane = tid & 31, wid = tid >> 5;
    const int warp_m = wid >> 1;    // 0..3 -> 32 rows each
    const int warp_n = wid & 1;     // 0..1 -> 64 cols each
    const int m_base = blockIdx.x * 128;
    const int g  = lane >> 2;       // accum row group
    const int tg = lane & 3;

    const uint32_t sa_hi = smem_u32(a_hi), sa_lo = smem_u32(a_lo);
    const uint32_t sb_hi = smem_u32(b_hi), sb_lo = smem_u32(b_lo);

    // ldmatrix lane -> address row/col components
    const int a_r = (lane & 7) + ((lane >> 3) & 1) * 8;  // m within 16
    const int a_k = ((lane >> 4) & 1) * 8;               // k offset 0/8
    const int b_k = (lane & 7) + ((lane >> 3) & 1) * 8;  // k within 16 (lanes&15)

    float acc[2][8][4];
    #pragma unroll
    for (int a = 0; a < 2; a++)
        #pragma unroll
        for (int b = 0; b < 8; b++)
            #pragma unroll
            for (int c = 0; c < 4; c++) acc[a][b][c] = 0.f;

    for (int kc = 0; kc < DIM; kc += KC) {
        // ---- A tile: 128 rows x 32 cols fp32 -> hi/lo bf16, [m][k] ----
        #pragma unroll
        for (int i = 0; i < 4; i++) {
            int id  = tid + i * 256;       // 1024 float4 slots
            int row = id >> 3;
            int c4  = (id & 7) * 4;
            float4 v = make_float4(0.f, 0.f, 0.f, 0.f);
            int gr = m_base + row;
            if (gr < NN) v = *(const float4*)(x + (size_t)gr * DIM + kc + c4);
            __nv_bfloat162 h01 = __floats2bfloat162_rn(v.x, v.y);
            __nv_bfloat162 h23 = __floats2bfloat162_rn(v.z, v.w);
            float2 f01 = __bfloat1622float2(h01);
            float2 f23 = __bfloat1622float2(h23);
            __nv_bfloat162 l01 = __floats2bfloat162_rn(v.x - f01.x, v.y - f01.y);
            __nv_bfloat162 l23 = __floats2bfloat162_rn(v.z - f23.x, v.w - f23.y);
            int o = row * ASTR + c4;
            *(__nv_bfloat162*)&a_hi[o]     = h01;
            *(__nv_bfloat162*)&a_hi[o + 2] = h23;
            *(__nv_bfloat162*)&a_lo[o]     = l01;
            *(__nv_bfloat162*)&a_lo[o + 2] = l23;
        }
        // ---- B tile: 32 rows x 128 cols, straight [k][n] (no transpose) ----
        #pragma unroll
        for (int i = 0; i < 4; i++) {
            int id = tid + i * 256;        // 1024 float4 slots
            int k  = id >> 5;              // 0..31
            int n4 = (id & 31) * 4;
            float4 v = *(const float4*)(W + (size_t)(kc + k) * DIM + n4);
            __nv_bfloat162 h01 = __floats2bfloat162_rn(v.x, v.y);
            __nv_bfloat162 h23 = __floats2bfloat162_rn(v.z, v.w);
            float2 f01 = __bfloat1622float2(h01);
            float2 f23 = __bfloat1622float2(h23);
            __nv_bfloat162 l01 = __floats2bfloat162_rn(v.x - f01.x, v.y - f01.y);
            __nv_bfloat162 l23 = __floats2bfloat162_rn(v.z - f23.x, v.w - f23.y);
            int o = k * BSTR + n4;
            *(__nv_bfloat162*)&b_hi[o]     = h01;
            *(__nv_bfloat162*)&b_hi[o + 2] = h23;
            *(__nv_bfloat162*)&b_lo[o]     = l01;
            *(__nv_bfloat162*)&b_lo[o + 2] = l23;
        }
        __syncthreads();

        #pragma unroll
        for (int kk = 0; kk < KC; kk += 16) {
            uint32_t Ahi[2][4], Alo[2][4];
            #pragma unroll
            for (int tm = 0; tm < 2; tm++) {
                int row = warp_m * 32 + tm * 16 + a_r;
                uint32_t off = (uint32_t)(row * ASTR + kk + a_k) * 2;
                ldmA(Ahi[tm], sa_hi + off);
                ldmA(Alo[tm], sa_lo + off);
            }
            #pragma unroll
            for (int tn = 0; tn < 8; tn++) {
                int n0 = warp_n * 64 + tn * 8;
                uint32_t boff = (uint32_t)((kk + b_k) * BSTR + n0) * 2;
                uint32_t bh0, bh1, bl0, bl1;
                ldmB(bh0, bh1, sb_hi + boff);
                ldmB(bl0, bl1, sb_lo + boff);
                #pragma unroll
                for (int tm = 0; tm < 2; tm++) {
                    mma16(acc[tm][tn], Ahi[tm], bh0, bh1);   // hi*hi
                    mma16(acc[tm][tn], Ahi[tm], bl0, bl1);   // hi*lo
                    mma16(acc[tm][tn], Alo[tm], bh0, bh1);   // lo*hi
                }
            }
        }
        __syncthreads();
    }

    // ---- epilogue: bias + store ----
    #pragma unroll
    for (int tm = 0; tm < 2; tm++) {
        int r = m_base + warp_m * 32 + tm * 16 + g;
        #pragma unroll
        for (int tn = 0; tn < 8; tn++) {
            int c = warp_n * 64 + tn * 8 + tg * 2;
            float b0 = bias[c], b1 = bias[c + 1];
            float v00 = acc[tm][tn][0] + b0, v01 = acc[tm][tn][1] + b1;
            float v10 = acc[tm][tn][2] + b0, v11 = acc[tm][tn][3] + b1;
            if (outf) {
                if (r < NN)
                    *(float2*)(outf + (size_t)r * DIM + c) = make_float2(v00, v01);
                if (r + 8 < NN)
                    *(float2*)(outf + (size_t)(r + 8) * DIM + c) = make_float2(v10, v11);
            } else {
                if (r < NN)
                    *(__nv_bfloat162*)(outb + (size_t)r * DIM + c) =
                        __floats2bfloat162_rn(v00, v01);
                if (r + 8 < NN)
                    *(__nv_bfloat162*)(outb + (size_t)(r + 8) * DIM + c) =
                        __floats2bfloat162_rn(v10, v11);
            }
        }
    }
}

// ---------------- fused attention: one warp per dst node ---------------------
__global__ void attn_kernel(float* __restrict__ dout) {
    int warp = (blockIdx.x * blockDim.x + threadIdx.x) >> 5;
    if (warp >= NN) return;
    int lane = threadIdx.x & 31;

    const float4 qv = *(const float4*)(g_q + (size_t)warp * DIM + lane * 4);
    float4 acc = make_float4(0.f, 0.f, 0.f, 0.f);
    float denom = 0.f;

    const int e0 = g_off[warp];
    const int e1 = g_off[warp + 1];
    const float inv_sqrt_c = 0.17677669529663688f;  // 1/sqrt(32)

    for (int j = e0; j < e1; ++j) {
        int s = g_csr[j];
        uint2 kr = *(const uint2*)(g_kb + (size_t)s * DIM + lane * 4);
        float2 k01 = __bfloat1622float2(*(__nv_bfloat162*)&kr.x);
        float2 k23 = __bfloat1622float2(*(__nv_bfloat162*)&kr.y);
        float p = qv.x * k01.x + qv.y * k01.y + qv.z * k23.x + qv.w * k23.y;
        p += __shfl_xor_sync(0xffffffffu, p, 1);
        p += __shfl_xor_sync(0xffffffffu, p, 2);
        p += __shfl_xor_sync(0xffffffffu, p, 4);
        float ex = __expf(p * inv_sqrt_c);
        uint2 vr = *(const uint2*)(g_vb + (size_t)s * DIM + lane * 4);
        float2 v01 = __bfloat1622float2(*(__nv_bfloat162*)&vr.x);
        float2 v23 = __bfloat1622float2(*(__nv_bfloat162*)&vr.y);
        acc.x += ex * v01.x; acc.y += ex * v01.y;
        acc.z += ex * v23.x; acc.w += ex * v23.y;
        denom += ex;
    }

    float inv = (denom > 0.f) ? (1.f / denom) : 0.f;
    float4* op = (float4*)(dout + (size_t)warp * DIM + lane * 4);
    float4 cur = *op;   // skip projection from GEMM
    cur.x += acc.x * inv; cur.y += acc.y * inv;
    cur.z += acc.z * inv; cur.w += acc.w * inv;
    *op = cur;
}

// ---------------- launch: single stream; GEMM is launch #6 for ncu -----------
extern "C" void kernel_launch(void* const* d_in, const int* in_sizes, int n_in,
                              void* d_out, int out_size) {
    const float* x   = (const float*)d_in[0];
    const void*  ei  = d_in[1];
    const float* Wq  = (const float*)d_in[2];
    const float* bq  = (const float*)d_in[3];
    const float* Wk  = (const float*)d_in[4];
    const float* bk  = (const float*)d_in[5];
    const float* Wv  = (const float*)d_in[6];
    const float* bv  = (const float*)d_in[7];
    const float* Ws  = (const float*)d_in[8];
    const float* bs  = (const float*)d_in[9];
    float* dout = (float*)d_out;

    init_kernel<<<(NN + 1023) / 1024, 1024>>>();      // 1
    detect_kernel<<<1, 1024>>>(ei);                   // 2
    hist_kernel<<<(EE + 255) / 256, 256>>>(ei);       // 3
    scan1_kernel<<<NB, 1024>>>();                     // 4
    scan2_kernel<<<1, 64>>>();                        // 5

    dim3 ggrid((NN + 127) / 128, 4);                  // 6 (ncu -s 5 -c 1)
    gemm_bf16x3_kernel<<<ggrid, 256>>>(x, Wq, bq, Wk, bk, Wv, bv, Ws, bs, dout);

    scan3_kernel<<<NB, 1024>>>();                     // 7
    fill_kernel<<<(EE + 255) / 256, 256>>>(ei);       // 8
    attn_kernel<<<(NN * 32 + 255) / 256, 256>>>(dout);// 9
}